// round 7
// baseline (speedup 1.0000x reference)
#include <cuda_runtime.h>
#include <cuda_bf16.h>
#include <cstdint>

// Problem dims
#define BV   64
#define TT   500
#define FIN  1250
#define KP   1280          // FIN padded for B
#define HH   512
#define OO   2
#define MM   (BV * TT)     // 32000

// Neuron constants
#define DSYN  0.9048374180359595f
#define DREF  0.36787944117144233f
#define THETA 10.0f

// Scratch (device globals: allocation-free rule)
__device__ __align__(16) __nv_bfloat16 g_w1b[(size_t)HH * KP];   // 1.3 MB
__device__ __align__(16) __nv_bfloat16 g_u1 [(size_t)MM * HH];   // 32 MB
__device__ __align__(16) __nv_bfloat16 g_s1 [(size_t)MM * HH];   // 32 MB
__device__ __align__(16) float          g_u2 [(size_t)MM * OO];  // 256 KB

// ---------------------------------------------------------------------------
// PTX helpers
// ---------------------------------------------------------------------------
__device__ __forceinline__ void ldsm_x4(uint32_t &r0, uint32_t &r1,
                                        uint32_t &r2, uint32_t &r3,
                                        uint32_t addr)
{
    asm volatile("ldmatrix.sync.aligned.m8n8.x4.shared.b16 {%0,%1,%2,%3}, [%4];"
                 : "=r"(r0), "=r"(r1), "=r"(r2), "=r"(r3) : "r"(addr));
}

__device__ __forceinline__ void mma16816(float* c, const uint32_t* a,
                                         const uint32_t b0, const uint32_t b1)
{
    asm volatile(
        "mma.sync.aligned.m16n8k16.row.col.f32.bf16.bf16.f32 "
        "{%0,%1,%2,%3}, {%4,%5,%6,%7}, {%8,%9}, {%0,%1,%2,%3};"
        : "+f"(c[0]), "+f"(c[1]), "+f"(c[2]), "+f"(c[3])
        : "r"(a[0]), "r"(a[1]), "r"(a[2]), "r"(a[3]), "r"(b0), "r"(b1));
}

__device__ __forceinline__ void cp_async16(uint32_t smem_addr, const void* gptr)
{
    asm volatile("cp.async.cg.shared.global [%0], [%1], 16;"
                 :: "r"(smem_addr), "l"(gptr));
}
__device__ __forceinline__ void cp_commit()
{
    asm volatile("cp.async.commit_group;");
}
__device__ __forceinline__ void cp_wait0()
{
    asm volatile("cp.async.wait_group 0;");
}

// ---------------------------------------------------------------------------
// K0: W1 fp32 -> bf16, pad K 1250 -> 1280 (1.3 MB; L2-resident thereafter)
// ---------------------------------------------------------------------------
__global__ __launch_bounds__(256) void cvt_w1_kernel(
    const float* __restrict__ W, __nv_bfloat16* __restrict__ Wb)
{
    long i = (long)blockIdx.x * blockDim.x + threadIdx.x;
    if (i >= (long)HH * KP) return;
    int  k = (int)(i % KP);
    long h = i / KP;
    float v = (k < FIN) ? W[h * FIN + k] : 0.0f;
    Wb[i] = __float2bfloat16(v);
}

// ---------------------------------------------------------------------------
// K1: U1[m,h] = sum_k X[m,k] * W1[h,k]   (bf16 HMMA, fp32 accum, bf16 out)
// BM=128, BN=256, BK=64. 8 warps as 2(m) x 4(n), warp tile 64x64
//   -> per k16 step: 8 ldsm feed 32 mma.
// A: fp32 LDG -> cvt -> packed bf16x2 regs -> STS, one chunk ahead.
// B: cp.async, double buffered. Rows padded to 72 bf16 (144B).
// ---------------------------------------------------------------------------
#define BM 128
#define BN 256
#define BK 64
#define LDA 72
#define ROWB (LDA * 2)             // 144 bytes/row
#define ABUFB (BM * ROWB)          // 18432
#define BBUFB (BN * ROWB)          // 36864
#define SMEM_GEMM (2 * ABUFB + 2 * BBUFB)   // 110592
#define NKCH (KP / BK)             // 20

__global__ __launch_bounds__(256, 1) void gemm1_mma_kernel(
    const float* __restrict__ X,
    const __nv_bfloat16* __restrict__ Wb,
    __nv_bfloat16* __restrict__ U)
{
    extern __shared__ __align__(16) char smem[];
    char* As = smem;
    char* Bs = smem + 2 * ABUFB;

    const int tid  = threadIdx.x;
    const int warp = tid >> 5;
    const int lane = tid & 31;
    const int wm   = warp >> 2;            // 0..1 -> m off wm*64
    const int wn   = warp & 3;             // 0..3 -> n off wn*64
    const int bm   = blockIdx.y * BM;
    const int bn   = blockIdx.x * BN;

    float acc[4][8][4];
#pragma unroll
    for (int i = 0; i < 4; i++)
#pragma unroll
        for (int j = 0; j < 8; j++)
#pragma unroll
            for (int q = 0; q < 4; q++) acc[i][j][q] = 0.0f;

    const uint32_t asB = (uint32_t)__cvta_generic_to_shared(As);
    const uint32_t bsB = (uint32_t)__cvta_generic_to_shared(Bs);

    // A: 128 rows x 32 float2 = 4096 units, 16/thread. row=(tid>>5)+j*8, c2=tid&31
    const int aRowL = tid >> 5;
    const int aC2   = tid & 31;
    // B: 256 rows x 128B = 2048 x16B, 8/thread. row=(tid>>3)+j*32, g=tid&7
    const int bRowL = tid >> 3;
    const int bG    = tid & 7;

    const float* Xb = X + (size_t)bm * FIN;

    uint32_t preA[16];                     // bf16x2 packed prefetch

    // ---- preload chunk 0
    {
#pragma unroll
        for (int j = 0; j < 16; j++) {
            int row = aRowL + j * 8;
            float2 v = *(const float2*)(Xb + (size_t)row * FIN + aC2 * 2);
            __nv_bfloat162 b2 = __float22bfloat162_rn(v);
            preA[j] = *(const uint32_t*)&b2;
        }
#pragma unroll
        for (int j = 0; j < 16; j++) {
            int row = aRowL + j * 8;
            *(uint32_t*)(As + row * ROWB + aC2 * 4) = preA[j];
        }
#pragma unroll
        for (int j = 0; j < 8; j++) {
            int row = bRowL + j * 32;
            cp_async16(bsB + (uint32_t)(row * ROWB + bG * 16),
                       Wb + (size_t)(bn + row) * KP + bG * 8);
        }
        cp_commit();
    }

    const uint32_t aRowOff = (uint32_t)(wm * 64 + (lane & 15));
    const uint32_t aColOff = (uint32_t)((lane >> 4) * 16);
    const uint32_t bRowOff = (uint32_t)(wn * 64 + ((lane >> 4) & 1) * 8 + (lane & 7));
    const uint32_t bColOff = (uint32_t)(((lane >> 3) & 1) * 16);

    for (int kt = 0; kt < NKCH; kt++) {
        cp_wait0();
        __syncthreads();                   // buffer kt&1 ready; nb free

        const int nb = (kt + 1) & 1;
        const bool more = (kt + 1 < NKCH);

        if (more) {
            const int kn = (kt + 1) * BK;
            if (kt + 1 < NKCH - 1) {
#pragma unroll
                for (int j = 0; j < 16; j++) {
                    int row = aRowL + j * 8;
                    float2 v = *(const float2*)(Xb + (size_t)row * FIN + kn + aC2 * 2);
                    __nv_bfloat162 b2 = __float22bfloat162_rn(v);
                    preA[j] = *(const uint32_t*)&b2;
                }
            } else {                        // last chunk: k 1216..1279
#pragma unroll
                for (int j = 0; j < 16; j++) {
                    int row = aRowL + j * 8;
                    int k   = kn + aC2 * 2;
                    float2 v = (k < FIN)
                        ? *(const float2*)(Xb + (size_t)row * FIN + k)
                        : make_float2(0.0f, 0.0f);
                    __nv_bfloat162 b2 = __float22bfloat162_rn(v);
                    preA[j] = *(const uint32_t*)&b2;
                }
            }
#pragma unroll
            for (int j = 0; j < 8; j++) {
                int row = bRowL + j * 32;
                cp_async16(bsB + (uint32_t)(nb * BBUFB + row * ROWB + bG * 16),
                           Wb + (size_t)(bn + row) * KP + kn + bG * 8);
            }
            cp_commit();
        } else {
            cp_commit();
        }

        const uint32_t aBase = asB + (uint32_t)((kt & 1) * ABUFB);
        const uint32_t bBase = bsB + (uint32_t)((kt & 1) * BBUFB);

#pragma unroll
        for (int ks = 0; ks < 4; ks++) {
            uint32_t a[4][4];
#pragma unroll
            for (int mt = 0; mt < 4; mt++) {
                uint32_t addr = aBase + (aRowOff + mt * 16) * ROWB
                                      + ks * 32 + aColOff;
                ldsm_x4(a[mt][0], a[mt][1], a[mt][2], a[mt][3], addr);
            }
            uint32_t b[4][4];
#pragma unroll
            for (int p = 0; p < 4; p++) {
                uint32_t addr = bBase + (bRowOff + p * 16) * ROWB
                                      + ks * 32 + bColOff;
                ldsm_x4(b[p][0], b[p][1], b[p][2], b[p][3], addr);
            }
#pragma unroll
            for (int mt = 0; mt < 4; mt++)
#pragma unroll
                for (int nt = 0; nt < 8; nt++)
                    mma16816(acc[mt][nt], a[mt],
                             b[nt >> 1][(nt & 1) * 2],
                             b[nt >> 1][(nt & 1) * 2 + 1]);
        }

        if (more) {
#pragma unroll
            for (int j = 0; j < 16; j++) {
                int row = aRowL + j * 8;
                *(uint32_t*)(As + nb * ABUFB + row * ROWB + aC2 * 4) = preA[j];
            }
        }
    }

    // epilogue: bf16 stores
    const int cr = lane >> 2;
    const int cc = (lane & 3) * 2;
#pragma unroll
    for (int mt = 0; mt < 4; mt++) {
#pragma unroll
        for (int nt = 0; nt < 8; nt++) {
            int row0 = bm + wm * 64 + mt * 16 + cr;
            int col  = bn + wn * 64 + nt * 8 + cc;
            __nv_bfloat162 v01 = __floats2bfloat162_rn(acc[mt][nt][0], acc[mt][nt][1]);
            __nv_bfloat162 v23 = __floats2bfloat162_rn(acc[mt][nt][2], acc[mt][nt][3]);
            *(__nv_bfloat162*)(U + (size_t)row0 * HH + col)       = v01;
            *(__nv_bfloat162*)(U + (size_t)(row0 + 8) * HH + col) = v23;
        }
    }
}

// ---------------------------------------------------------------------------
// K2: fused PSP + spike scan, layer 1. One thread runs TWO adjacent h chains
// via bfloat162 loads/stores. Two-named-buffer pipeline, static indices.
// ---------------------------------------------------------------------------
#define SCH 10
__global__ __launch_bounds__(128) void scan1_kernel(
    const __nv_bfloat16* __restrict__ U1, __nv_bfloat16* __restrict__ S1)
{
    const int b  = blockIdx.x;
    const int h2 = blockIdx.y * 128 + threadIdx.x;      // pair index 0..255
    const __nv_bfloat162* up =
        (const __nv_bfloat162*)(U1 + (size_t)b * TT * HH) + h2;
    __nv_bfloat162* sp =
        (__nv_bfloat162*)(S1 + (size_t)b * TT * HH) + h2;
    const int STR = HH / 2;                              // 256 pairs per t

    __nv_bfloat162 b0[SCH], b1[SCH];
#pragma unroll
    for (int j = 0; j < SCH; j++) b0[j] = up[(size_t)j * STR];

    float p0 = 0.0f, r0 = 0.0f, p1 = 0.0f, r1 = 0.0f;
    const int NC = TT / SCH;             // 50 (even)
    for (int c = 0; c < NC; c += 2) {
        {
            const __nv_bfloat162* nx = up + (size_t)(c + 1) * SCH * STR;
#pragma unroll
            for (int j = 0; j < SCH; j++) b1[j] = nx[(size_t)j * STR];
        }
        {
            __nv_bfloat162* so = sp + (size_t)c * SCH * STR;
#pragma unroll
            for (int j = 0; j < SCH; j++) {
                float2 u = __bfloat1622float2(b0[j]);
                p0 = DSYN * p0 + u.x;
                p1 = DSYN * p1 + u.y;
                float s0 = ((p0 + r0) >= THETA) ? 1.0f : 0.0f;
                float s1 = ((p1 + r1) >= THETA) ? 1.0f : 0.0f;
                r0 = DREF * (r0 - 2.0f * THETA * s0);
                r1 = DREF * (r1 - 2.0f * THETA * s1);
                so[(size_t)j * STR] = __floats2bfloat162_rn(s0, s1);
            }
        }
        if (c + 2 < NC) {
            const __nv_bfloat162* nx = up + (size_t)(c + 2) * SCH * STR;
#pragma unroll
            for (int j = 0; j < SCH; j++) b0[j] = nx[(size_t)j * STR];
        }
        {
            __nv_bfloat162* so = sp + (size_t)(c + 1) * SCH * STR;
#pragma unroll
            for (int j = 0; j < SCH; j++) {
                float2 u = __bfloat1622float2(b1[j]);
                p0 = DSYN * p0 + u.x;
                p1 = DSYN * p1 + u.y;
                float s0 = ((p0 + r0) >= THETA) ? 1.0f : 0.0f;
                float s1 = ((p1 + r1) >= THETA) ? 1.0f : 0.0f;
                r0 = DREF * (r0 - 2.0f * THETA * s0);
                r1 = DREF * (r1 - 2.0f * THETA * s1);
                so[(size_t)j * STR] = __floats2bfloat162_rn(s0, s1);
            }
        }
    }
}

// ---------------------------------------------------------------------------
// K3: U2[m,o] = sum_h S1[m,h] * W2[o,h]. W2 held in REGISTERS (no LDS);
// each warp processes 8 rows to amortize the W2 load. 500 blocks x 256.
// ---------------------------------------------------------------------------
__global__ __launch_bounds__(256) void gemm2_kernel(
    const __nv_bfloat16* __restrict__ S1, const float* __restrict__ W2,
    float* __restrict__ U2)
{
    const int warp = threadIdx.x >> 5;
    const int lane = threadIdx.x & 31;
    const int hb   = lane * 16;

    float w0[16], w1[16];
#pragma unroll
    for (int q = 0; q < 16; q++) {
        w0[q] = W2[hb + q];
        w1[q] = W2[HH + hb + q];
    }

    const int mBase = blockIdx.x * 64 + warp * 8;
#pragma unroll
    for (int rr = 0; rr < 8; rr++) {
        const int m = mBase + rr;
        const __nv_bfloat16* s = S1 + (size_t)m * HH + hb;
        uint4 v0 = *(const uint4*)(s);
        uint4 v1 = *(const uint4*)(s + 8);
        const uint32_t w[8] = {v0.x, v0.y, v0.z, v0.w, v1.x, v1.y, v1.z, v1.w};

        float a0 = 0.0f, a1 = 0.0f;
#pragma unroll
        for (int q = 0; q < 8; q++) {
            float2 sv = __bfloat1622float2(*(const __nv_bfloat162*)&w[q]);
            a0 += sv.x * w0[q * 2] + sv.y * w0[q * 2 + 1];
            a1 += sv.x * w1[q * 2] + sv.y * w1[q * 2 + 1];
        }
#pragma unroll
        for (int off = 16; off > 0; off >>= 1) {
            a0 += __shfl_xor_sync(0xFFFFFFFFu, a0, off);
            a1 += __shfl_xor_sync(0xFFFFFFFFu, a1, off);
        }
        if (lane == 0)
            *(float2*)(U2 + (size_t)m * OO) = make_float2(a0, a1);
    }
}

// ---------------------------------------------------------------------------
// K4: scan layer 2. Explicit two-named-buffer pipeline.
// ---------------------------------------------------------------------------
#define SC2 20
__global__ __launch_bounds__(128) void scan2_kernel(
    const float* __restrict__ U2, float* __restrict__ out)
{
    const int i = threadIdx.x;
    const int b = i >> 1;
    const int o = i & 1;
    const float* up = U2  + (size_t)b * TT * OO + o;
    float*       op = out + (size_t)b * TT * OO + o;

    float b0[SC2], b1[SC2];
#pragma unroll
    for (int j = 0; j < SC2; j++) b0[j] = up[(size_t)j * OO];

    float p = 0.0f, r = 0.0f;
    const int NC = TT / SC2;             // 25 (odd)
    for (int c = 0; c < NC; c += 2) {
        if (c + 1 < NC) {
            const float* nx = up + (size_t)(c + 1) * SC2 * OO;
#pragma unroll
            for (int j = 0; j < SC2; j++) b1[j] = nx[(size_t)j * OO];
        }
        {
            float* oo = op + (size_t)c * SC2 * OO;
#pragma unroll
            for (int j = 0; j < SC2; j++) {
                p = DSYN * p + b0[j];
                float v = p + r;
                float s = (v >= THETA) ? 1.0f : 0.0f;
                r = DREF * (r - 2.0f * THETA * s);
                oo[(size_t)j * OO] = s;
            }
        }
        if (c + 2 < NC) {
            const float* nx = up + (size_t)(c + 2) * SC2 * OO;
#pragma unroll
            for (int j = 0; j < SC2; j++) b0[j] = nx[(size_t)j * OO];
        }
        if (c + 1 < NC) {
            float* oo = op + (size_t)(c + 1) * SC2 * OO;
#pragma unroll
            for (int j = 0; j < SC2; j++) {
                p = DSYN * p + b1[j];
                float v = p + r;
                float s = (v >= THETA) ? 1.0f : 0.0f;
                r = DREF * (r - 2.0f * THETA * s);
                oo[(size_t)j * OO] = s;
            }
        }
    }
}

// ---------------------------------------------------------------------------
extern "C" void kernel_launch(void* const* d_in, const int* in_sizes, int n_in,
                              void* d_out, int out_size)
{
    const float* x  = (const float*)d_in[0];   // (64, 500, 1250)
    const float* W1 = (const float*)d_in[1];   // (512, 1250)
    const float* W2 = (const float*)d_in[2];   // (2, 512)
    float* out = (float*)d_out;                // (64, 500, 2)

    __nv_bfloat16* w1b; cudaGetSymbolAddress((void**)&w1b, g_w1b);
    __nv_bfloat16* u1;  cudaGetSymbolAddress((void**)&u1,  g_u1);
    __nv_bfloat16* s1;  cudaGetSymbolAddress((void**)&s1,  g_s1);
    float*         u2;  cudaGetSymbolAddress((void**)&u2,  g_u2);

    {
        long n = (long)HH * KP;
        cvt_w1_kernel<<<(unsigned)((n + 255) / 256), 256>>>(W1, w1b);
    }

    cudaFuncSetAttribute(gemm1_mma_kernel,
                         cudaFuncAttributeMaxDynamicSharedMemorySize, SMEM_GEMM);
    dim3 g1(HH / BN, MM / BM);                // (2, 250)
    gemm1_mma_kernel<<<g1, 256, SMEM_GEMM>>>(x, w1b, u1);

    dim3 g2(BV, HH / 256);                    // (64, 2)
    scan1_kernel<<<g2, 128>>>(u1, s1);

    gemm2_kernel<<<MM / 64, 256>>>(s1, W2, u2);

    scan2_kernel<<<1, 128>>>(u2, out);
}

// round 8
// speedup vs baseline: 1.6717x; 1.6717x over previous
#include <cuda_runtime.h>
#include <cuda_bf16.h>
#include <cstdint>

// Problem dims
#define BV   64
#define TT   500
#define FIN  1250
#define KP   1280          // FIN padded for B
#define HH   512
#define OO   2
#define MM   (BV * TT)     // 32000

// Neuron constants
#define DSYN  0.9048374180359595f
#define DREF  0.36787944117144233f
#define THETA 10.0f

// Scratch (device globals: allocation-free rule)
__device__ __align__(16) __nv_bfloat16 g_w1b[(size_t)HH * KP];   // 1.3 MB
__device__ __align__(16) __nv_bfloat16 g_u1 [(size_t)MM * HH];   // 32 MB
__device__ __align__(16) __nv_bfloat16 g_s1 [(size_t)MM * HH];   // 32 MB
__device__ __align__(16) float          g_u2 [(size_t)MM * OO];  // 256 KB

// ---------------------------------------------------------------------------
// PTX helpers
// ---------------------------------------------------------------------------
__device__ __forceinline__ void ldsm_x4(uint32_t &r0, uint32_t &r1,
                                        uint32_t &r2, uint32_t &r3,
                                        uint32_t addr)
{
    asm volatile("ldmatrix.sync.aligned.m8n8.x4.shared.b16 {%0,%1,%2,%3}, [%4];"
                 : "=r"(r0), "=r"(r1), "=r"(r2), "=r"(r3) : "r"(addr));
}

__device__ __forceinline__ void mma16816(float* c, const uint32_t* a,
                                         const uint32_t b0, const uint32_t b1)
{
    asm volatile(
        "mma.sync.aligned.m16n8k16.row.col.f32.bf16.bf16.f32 "
        "{%0,%1,%2,%3}, {%4,%5,%6,%7}, {%8,%9}, {%0,%1,%2,%3};"
        : "+f"(c[0]), "+f"(c[1]), "+f"(c[2]), "+f"(c[3])
        : "r"(a[0]), "r"(a[1]), "r"(a[2]), "r"(a[3]), "r"(b0), "r"(b1));
}

__device__ __forceinline__ void cp_async16(uint32_t smem_addr, const void* gptr)
{
    asm volatile("cp.async.cg.shared.global [%0], [%1], 16;"
                 :: "r"(smem_addr), "l"(gptr));
}
__device__ __forceinline__ void cp_commit()
{
    asm volatile("cp.async.commit_group;");
}
__device__ __forceinline__ void cp_wait0()
{
    asm volatile("cp.async.wait_group 0;");
}

// ---------------------------------------------------------------------------
// K0: W1 fp32 -> bf16, pad K 1250 -> 1280 (1.3 MB; L2-resident thereafter)
// ---------------------------------------------------------------------------
__global__ __launch_bounds__(256) void cvt_w1_kernel(
    const float* __restrict__ W, __nv_bfloat16* __restrict__ Wb)
{
    long i = (long)blockIdx.x * blockDim.x + threadIdx.x;
    if (i >= (long)HH * KP) return;
    int  k = (int)(i % KP);
    long h = i / KP;
    float v = (k < FIN) ? W[h * FIN + k] : 0.0f;
    Wb[i] = __float2bfloat16(v);
}

// ---------------------------------------------------------------------------
// K1: U1[m,h] = sum_k X[m,k] * W1[h,k]   (bf16 HMMA, fp32 accum, bf16 out)
// R6-proven config: BM=64, BN=256, BK=64, occ 2. 8 warps as 2(m) x 4(n),
// warp tile 32x64. A: fp32 LDG -> regs -> bf16 STS, one chunk ahead.
// B: cp.async, double buffered. Rows padded to 72 bf16 (144B).
// ---------------------------------------------------------------------------
#define BM 64
#define BN 256
#define BK 64
#define LDA 72
#define ROWB (LDA * 2)             // 144 bytes/row
#define ABUFB (BM * ROWB)          // 9216
#define BBUFB (BN * ROWB)          // 36864
#define SMEM_GEMM (2 * ABUFB + 2 * BBUFB)   // 92160
#define NKCH (KP / BK)             // 20

__global__ __launch_bounds__(256, 2) void gemm1_mma_kernel(
    const float* __restrict__ X,
    const __nv_bfloat16* __restrict__ Wb,
    __nv_bfloat16* __restrict__ U)
{
    extern __shared__ __align__(16) char smem[];
    char* As = smem;
    char* Bs = smem + 2 * ABUFB;

    const int tid  = threadIdx.x;
    const int warp = tid >> 5;
    const int lane = tid & 31;
    const int wm   = warp >> 2;            // 0..1 -> m off wm*32
    const int wn   = warp & 3;             // 0..3 -> n off wn*64
    const int bm   = blockIdx.y * BM;
    const int bn   = blockIdx.x * BN;

    float acc[2][8][4];
#pragma unroll
    for (int i = 0; i < 2; i++)
#pragma unroll
        for (int j = 0; j < 8; j++)
#pragma unroll
            for (int q = 0; q < 4; q++) acc[i][j][q] = 0.0f;

    const uint32_t asB = (uint32_t)__cvta_generic_to_shared(As);
    const uint32_t bsB = (uint32_t)__cvta_generic_to_shared(Bs);

    // A: 64 rows x 32 float2 = 2048 units, 8/thread. row=(tid>>5)+j*8, c2=tid&31
    const int aRowL = tid >> 5;
    const int aC2   = tid & 31;
    // B: 256 rows x 128B = 2048 x16B, 8/thread. row=(tid>>3)+j*32, g=tid&7
    const int bRowL = tid >> 3;
    const int bG    = tid & 7;

    const float* Xb = X + (size_t)bm * FIN;

    float2 pre[8];

    // ---- preload chunk 0
    {
#pragma unroll
        for (int j = 0; j < 8; j++) {
            int row = aRowL + j * 8;
            pre[j] = *(const float2*)(Xb + (size_t)row * FIN + aC2 * 2);
        }
#pragma unroll
        for (int j = 0; j < 8; j++) {
            int row = aRowL + j * 8;
            __nv_bfloat162 b2 = __float22bfloat162_rn(pre[j]);
            *(__nv_bfloat162*)(As + row * ROWB + aC2 * 4) = b2;
        }
#pragma unroll
        for (int j = 0; j < 8; j++) {
            int row = bRowL + j * 32;
            cp_async16(bsB + (uint32_t)(row * ROWB + bG * 16),
                       Wb + (size_t)(bn + row) * KP + bG * 8);
        }
        cp_commit();
    }

    const uint32_t aRowOff = (uint32_t)(wm * 32 + (lane & 15));
    const uint32_t aColOff = (uint32_t)((lane >> 4) * 16);
    const uint32_t bRowOff = (uint32_t)(wn * 64 + ((lane >> 4) & 1) * 8 + (lane & 7));
    const uint32_t bColOff = (uint32_t)(((lane >> 3) & 1) * 16);

    for (int kt = 0; kt < NKCH; kt++) {
        cp_wait0();
        __syncthreads();                   // buffer kt&1 ready; nb free

        const int nb = (kt + 1) & 1;
        const bool more = (kt + 1 < NKCH);

        if (more) {
            const int kn = (kt + 1) * BK;
            if (kt + 1 < NKCH - 1) {
#pragma unroll
                for (int j = 0; j < 8; j++) {
                    int row = aRowL + j * 8;
                    pre[j] = *(const float2*)(Xb + (size_t)row * FIN + kn + aC2 * 2);
                }
            } else {                        // last chunk: k 1216..1279
#pragma unroll
                for (int j = 0; j < 8; j++) {
                    int row = aRowL + j * 8;
                    int k   = kn + aC2 * 2;
                    pre[j] = (k < FIN)
                        ? *(const float2*)(Xb + (size_t)row * FIN + k)
                        : make_float2(0.0f, 0.0f);
                }
            }
#pragma unroll
            for (int j = 0; j < 8; j++) {
                int row = bRowL + j * 32;
                cp_async16(bsB + (uint32_t)(nb * BBUFB + row * ROWB + bG * 16),
                           Wb + (size_t)(bn + row) * KP + kn + bG * 8);
            }
            cp_commit();
        } else {
            cp_commit();
        }

        const uint32_t aBase = asB + (uint32_t)((kt & 1) * ABUFB);
        const uint32_t bBase = bsB + (uint32_t)((kt & 1) * BBUFB);

#pragma unroll
        for (int ks = 0; ks < 4; ks++) {
            uint32_t a[2][4];
#pragma unroll
            for (int mt = 0; mt < 2; mt++) {
                uint32_t addr = aBase + (aRowOff + mt * 16) * ROWB
                                      + ks * 32 + aColOff;
                ldsm_x4(a[mt][0], a[mt][1], a[mt][2], a[mt][3], addr);
            }
            uint32_t b[4][4];
#pragma unroll
            for (int p = 0; p < 4; p++) {
                uint32_t addr = bBase + (bRowOff + p * 16) * ROWB
                                      + ks * 32 + bColOff;
                ldsm_x4(b[p][0], b[p][1], b[p][2], b[p][3], addr);
            }
#pragma unroll
            for (int mt = 0; mt < 2; mt++)
#pragma unroll
                for (int nt = 0; nt < 8; nt++)
                    mma16816(acc[mt][nt], a[mt],
                             b[nt >> 1][(nt & 1) * 2],
                             b[nt >> 1][(nt & 1) * 2 + 1]);
        }

        if (more) {
#pragma unroll
            for (int j = 0; j < 8; j++) {
                int row = aRowL + j * 8;
                __nv_bfloat162 b2 = __float22bfloat162_rn(pre[j]);
                *(__nv_bfloat162*)(As + nb * ABUFB + row * ROWB + aC2 * 4) = b2;
            }
        }
    }

    // epilogue: bf16 stores
    const int cr = lane >> 2;
    const int cc = (lane & 3) * 2;
#pragma unroll
    for (int mt = 0; mt < 2; mt++) {
#pragma unroll
        for (int nt = 0; nt < 8; nt++) {
            int row0 = bm + wm * 32 + mt * 16 + cr;
            int col  = bn + wn * 64 + nt * 8 + cc;
            __nv_bfloat162 v01 = __floats2bfloat162_rn(acc[mt][nt][0], acc[mt][nt][1]);
            __nv_bfloat162 v23 = __floats2bfloat162_rn(acc[mt][nt][2], acc[mt][nt][3]);
            *(__nv_bfloat162*)(U + (size_t)row0 * HH + col)       = v01;
            *(__nv_bfloat162*)(U + (size_t)(row0 + 8) * HH + col) = v23;
        }
    }
}

// ---------------------------------------------------------------------------
// K2: fused PSP + spike scan, layer 1. One thread runs TWO adjacent h chains
// via bfloat162 loads/stores. Two-named-buffer pipeline, static indices.
// ---------------------------------------------------------------------------
#define SCH 10
__global__ __launch_bounds__(128) void scan1_kernel(
    const __nv_bfloat16* __restrict__ U1, __nv_bfloat16* __restrict__ S1)
{
    const int b  = blockIdx.x;
    const int h2 = blockIdx.y * 128 + threadIdx.x;      // pair index 0..255
    const __nv_bfloat162* up =
        (const __nv_bfloat162*)(U1 + (size_t)b * TT * HH) + h2;
    __nv_bfloat162* sp =
        (__nv_bfloat162*)(S1 + (size_t)b * TT * HH) + h2;
    const int STR = HH / 2;                              // 256 pairs per t

    __nv_bfloat162 b0[SCH], b1[SCH];
#pragma unroll
    for (int j = 0; j < SCH; j++) b0[j] = up[(size_t)j * STR];

    float p0 = 0.0f, r0 = 0.0f, p1 = 0.0f, r1 = 0.0f;
    const int NC = TT / SCH;             // 50 (even)
    for (int c = 0; c < NC; c += 2) {
        {
            const __nv_bfloat162* nx = up + (size_t)(c + 1) * SCH * STR;
#pragma unroll
            for (int j = 0; j < SCH; j++) b1[j] = nx[(size_t)j * STR];
        }
        {
            __nv_bfloat162* so = sp + (size_t)c * SCH * STR;
#pragma unroll
            for (int j = 0; j < SCH; j++) {
                float2 u = __bfloat1622float2(b0[j]);
                p0 = DSYN * p0 + u.x;
                p1 = DSYN * p1 + u.y;
                float s0 = ((p0 + r0) >= THETA) ? 1.0f : 0.0f;
                float s1 = ((p1 + r1) >= THETA) ? 1.0f : 0.0f;
                r0 = DREF * (r0 - 2.0f * THETA * s0);
                r1 = DREF * (r1 - 2.0f * THETA * s1);
                so[(size_t)j * STR] = __floats2bfloat162_rn(s0, s1);
            }
        }
        if (c + 2 < NC) {
            const __nv_bfloat162* nx = up + (size_t)(c + 2) * SCH * STR;
#pragma unroll
            for (int j = 0; j < SCH; j++) b0[j] = nx[(size_t)j * STR];
        }
        {
            __nv_bfloat162* so = sp + (size_t)(c + 1) * SCH * STR;
#pragma unroll
            for (int j = 0; j < SCH; j++) {
                float2 u = __bfloat1622float2(b1[j]);
                p0 = DSYN * p0 + u.x;
                p1 = DSYN * p1 + u.y;
                float s0 = ((p0 + r0) >= THETA) ? 1.0f : 0.0f;
                float s1 = ((p1 + r1) >= THETA) ? 1.0f : 0.0f;
                r0 = DREF * (r0 - 2.0f * THETA * s0);
                r1 = DREF * (r1 - 2.0f * THETA * s1);
                so[(size_t)j * STR] = __floats2bfloat162_rn(s0, s1);
            }
        }
    }
}

// ---------------------------------------------------------------------------
// K3: U2[m,o] = sum_h S1[m,h] * W2[o,h]. Warp per row (R5-proven pattern):
// lane-strided h = lane + 32i -> conflict-free smem W2, coalesced s1.
// ---------------------------------------------------------------------------
__global__ __launch_bounds__(256) void gemm2_kernel(
    const __nv_bfloat16* __restrict__ S1, const float* __restrict__ W2,
    float* __restrict__ U2)
{
    __shared__ float w2s[OO * HH];
    for (int i = threadIdx.x; i < OO * HH; i += blockDim.x) w2s[i] = W2[i];
    __syncthreads();

    const int gwarp = (blockIdx.x * blockDim.x + threadIdx.x) >> 5;
    const int lane  = threadIdx.x & 31;
    if (gwarp >= MM) return;

    const __nv_bfloat16* s = S1 + (size_t)gwarp * HH;
    float a0 = 0.0f, a1 = 0.0f;
#pragma unroll
    for (int h = lane; h < HH; h += 32) {
        float sv = __bfloat162float(s[h]);
        a0 += sv * w2s[h];
        a1 += sv * w2s[HH + h];
    }
#pragma unroll
    for (int off = 16; off > 0; off >>= 1) {
        a0 += __shfl_xor_sync(0xFFFFFFFFu, a0, off);
        a1 += __shfl_xor_sync(0xFFFFFFFFu, a1, off);
    }
    if (lane == 0) {
        U2[(size_t)gwarp * OO + 0] = a0;
        U2[(size_t)gwarp * OO + 1] = a1;
    }
}

// ---------------------------------------------------------------------------
// K4: scan layer 2. Explicit two-named-buffer pipeline.
// ---------------------------------------------------------------------------
#define SC2 20
__global__ __launch_bounds__(128) void scan2_kernel(
    const float* __restrict__ U2, float* __restrict__ out)
{
    const int i = threadIdx.x;
    const int b = i >> 1;
    const int o = i & 1;
    const float* up = U2  + (size_t)b * TT * OO + o;
    float*       op = out + (size_t)b * TT * OO + o;

    float b0[SC2], b1[SC2];
#pragma unroll
    for (int j = 0; j < SC2; j++) b0[j] = up[(size_t)j * OO];

    float p = 0.0f, r = 0.0f;
    const int NC = TT / SC2;             // 25 (odd)
    for (int c = 0; c < NC; c += 2) {
        if (c + 1 < NC) {
            const float* nx = up + (size_t)(c + 1) * SC2 * OO;
#pragma unroll
            for (int j = 0; j < SC2; j++) b1[j] = nx[(size_t)j * OO];
        }
        {
            float* oo = op + (size_t)c * SC2 * OO;
#pragma unroll
            for (int j = 0; j < SC2; j++) {
                p = DSYN * p + b0[j];
                float v = p + r;
                float s = (v >= THETA) ? 1.0f : 0.0f;
                r = DREF * (r - 2.0f * THETA * s);
                oo[(size_t)j * OO] = s;
            }
        }
        if (c + 2 < NC) {
            const float* nx = up + (size_t)(c + 2) * SC2 * OO;
#pragma unroll
            for (int j = 0; j < SC2; j++) b0[j] = nx[(size_t)j * OO];
        }
        if (c + 1 < NC) {
            float* oo = op + (size_t)(c + 1) * SC2 * OO;
#pragma unroll
            for (int j = 0; j < SC2; j++) {
                p = DSYN * p + b1[j];
                float v = p + r;
                float s = (v >= THETA) ? 1.0f : 0.0f;
                r = DREF * (r - 2.0f * THETA * s);
                oo[(size_t)j * OO] = s;
            }
        }
    }
}

// ---------------------------------------------------------------------------
extern "C" void kernel_launch(void* const* d_in, const int* in_sizes, int n_in,
                              void* d_out, int out_size)
{
    const float* x  = (const float*)d_in[0];   // (64, 500, 1250)
    const float* W1 = (const float*)d_in[1];   // (512, 1250)
    const float* W2 = (const float*)d_in[2];   // (2, 512)
    float* out = (float*)d_out;                // (64, 500, 2)

    __nv_bfloat16* w1b; cudaGetSymbolAddress((void**)&w1b, g_w1b);
    __nv_bfloat16* u1;  cudaGetSymbolAddress((void**)&u1,  g_u1);
    __nv_bfloat16* s1;  cudaGetSymbolAddress((void**)&s1,  g_s1);
    float*         u2;  cudaGetSymbolAddress((void**)&u2,  g_u2);

    {
        long n = (long)HH * KP;
        cvt_w1_kernel<<<(unsigned)((n + 255) / 256), 256>>>(W1, w1b);
    }

    cudaFuncSetAttribute(gemm1_mma_kernel,
                         cudaFuncAttributeMaxDynamicSharedMemorySize, SMEM_GEMM);
    dim3 g1(HH / BN, MM / BM);                // (2, 500)
    gemm1_mma_kernel<<<g1, 256, SMEM_GEMM>>>(x, w1b, u1);

    dim3 g2(BV, HH / 256);                    // (64, 2)
    scan1_kernel<<<g2, 128>>>(u1, s1);

    gemm2_kernel<<<(MM * 32 + 255) / 256, 256>>>(s1, W2, u2);

    scan2_kernel<<<1, 128>>>(u2, out);
}

// round 9
// speedup vs baseline: 1.9906x; 1.1908x over previous
#include <cuda_runtime.h>
#include <cuda_bf16.h>
#include <cstdint>

// Problem dims
#define BV   64
#define TT   500
#define FIN  1250
#define KP   1280          // FIN padded for B
#define HH   512
#define OO   2
#define MM   (BV * TT)     // 32000

// Neuron constants
#define DSYN  0.9048374180359595f
#define DREF  0.36787944117144233f
#define THETA 10.0f

// Scratch (device globals: allocation-free rule)
__device__ __align__(16) __nv_bfloat16 g_w1b[(size_t)HH * KP];   // 1.3 MB
__device__ __align__(16) __nv_bfloat16 g_u1 [(size_t)MM * HH];   // 32 MB
__device__ __align__(16) __nv_bfloat16 g_s1 [(size_t)MM * HH];   // 32 MB
__device__ __align__(16) float          g_u2 [(size_t)MM * OO];  // 256 KB

// ---------------------------------------------------------------------------
// PTX helpers
// ---------------------------------------------------------------------------
__device__ __forceinline__ void ldsm_x4(uint32_t &r0, uint32_t &r1,
                                        uint32_t &r2, uint32_t &r3,
                                        uint32_t addr)
{
    asm volatile("ldmatrix.sync.aligned.m8n8.x4.shared.b16 {%0,%1,%2,%3}, [%4];"
                 : "=r"(r0), "=r"(r1), "=r"(r2), "=r"(r3) : "r"(addr));
}

__device__ __forceinline__ void mma16816(float* c, const uint32_t* a,
                                         const uint32_t b0, const uint32_t b1)
{
    asm volatile(
        "mma.sync.aligned.m16n8k16.row.col.f32.bf16.bf16.f32 "
        "{%0,%1,%2,%3}, {%4,%5,%6,%7}, {%8,%9}, {%0,%1,%2,%3};"
        : "+f"(c[0]), "+f"(c[1]), "+f"(c[2]), "+f"(c[3])
        : "r"(a[0]), "r"(a[1]), "r"(a[2]), "r"(a[3]), "r"(b0), "r"(b1));
}

__device__ __forceinline__ void cp_async16(uint32_t smem_addr, const void* gptr)
{
    asm volatile("cp.async.cg.shared.global [%0], [%1], 16;"
                 :: "r"(smem_addr), "l"(gptr));
}
__device__ __forceinline__ void cp_commit()
{
    asm volatile("cp.async.commit_group;");
}
__device__ __forceinline__ void cp_wait0()
{
    asm volatile("cp.async.wait_group 0;");
}

// ---------------------------------------------------------------------------
// K0: W1 fp32 -> bf16, pad K 1250 -> 1280 (1.3 MB; L2-resident thereafter)
// ---------------------------------------------------------------------------
__global__ __launch_bounds__(256) void cvt_w1_kernel(
    const float* __restrict__ W, __nv_bfloat16* __restrict__ Wb)
{
    long i = (long)blockIdx.x * blockDim.x + threadIdx.x;
    if (i >= (long)HH * KP) return;
    int  k = (int)(i % KP);
    long h = i / KP;
    float v = (k < FIN) ? W[h * FIN + k] : 0.0f;
    Wb[i] = __float2bfloat16(v);
}

// ---------------------------------------------------------------------------
// K1: U1[m,h] = sum_k X[m,k] * W1[h,k]   (bf16 HMMA, fp32 accum, bf16 out)
// R6-proven config: BM=64, BN=256, BK=64, occ 2. 8 warps as 2(m) x 4(n),
// warp tile 32x64. A: fp32 LDG -> regs -> bf16 STS, one chunk ahead.
// B: cp.async, double buffered. Rows padded to 72 bf16 (144B).
// ---------------------------------------------------------------------------
#define BM 64
#define BN 256
#define BK 64
#define LDA 72
#define ROWB (LDA * 2)             // 144 bytes/row
#define ABUFB (BM * ROWB)          // 9216
#define BBUFB (BN * ROWB)          // 36864
#define SMEM_GEMM (2 * ABUFB + 2 * BBUFB)   // 92160
#define NKCH (KP / BK)             // 20

__global__ __launch_bounds__(256, 2) void gemm1_mma_kernel(
    const float* __restrict__ X,
    const __nv_bfloat16* __restrict__ Wb,
    __nv_bfloat16* __restrict__ U)
{
    extern __shared__ __align__(16) char smem[];
    char* As = smem;
    char* Bs = smem + 2 * ABUFB;

    const int tid  = threadIdx.x;
    const int warp = tid >> 5;
    const int lane = tid & 31;
    const int wm   = warp >> 2;            // 0..1 -> m off wm*32
    const int wn   = warp & 3;             // 0..3 -> n off wn*64
    const int bm   = blockIdx.y * BM;
    const int bn   = blockIdx.x * BN;

    float acc[2][8][4];
#pragma unroll
    for (int i = 0; i < 2; i++)
#pragma unroll
        for (int j = 0; j < 8; j++)
#pragma unroll
            for (int q = 0; q < 4; q++) acc[i][j][q] = 0.0f;

    const uint32_t asB = (uint32_t)__cvta_generic_to_shared(As);
    const uint32_t bsB = (uint32_t)__cvta_generic_to_shared(Bs);

    // A: 64 rows x 32 float2 = 2048 units, 8/thread. row=(tid>>5)+j*8, c2=tid&31
    const int aRowL = tid >> 5;
    const int aC2   = tid & 31;
    // B: 256 rows x 128B = 2048 x16B, 8/thread. row=(tid>>3)+j*32, g=tid&7
    const int bRowL = tid >> 3;
    const int bG    = tid & 7;

    const float* Xb = X + (size_t)bm * FIN;

    float2 pre[8];

    // ---- preload chunk 0
    {
#pragma unroll
        for (int j = 0; j < 8; j++) {
            int row = aRowL + j * 8;
            pre[j] = *(const float2*)(Xb + (size_t)row * FIN + aC2 * 2);
        }
#pragma unroll
        for (int j = 0; j < 8; j++) {
            int row = aRowL + j * 8;
            __nv_bfloat162 b2 = __float22bfloat162_rn(pre[j]);
            *(__nv_bfloat162*)(As + row * ROWB + aC2 * 4) = b2;
        }
#pragma unroll
        for (int j = 0; j < 8; j++) {
            int row = bRowL + j * 32;
            cp_async16(bsB + (uint32_t)(row * ROWB + bG * 16),
                       Wb + (size_t)(bn + row) * KP + bG * 8);
        }
        cp_commit();
    }

    const uint32_t aRowOff = (uint32_t)(wm * 32 + (lane & 15));
    const uint32_t aColOff = (uint32_t)((lane >> 4) * 16);
    const uint32_t bRowOff = (uint32_t)(wn * 64 + ((lane >> 4) & 1) * 8 + (lane & 7));
    const uint32_t bColOff = (uint32_t)(((lane >> 3) & 1) * 16);

    for (int kt = 0; kt < NKCH; kt++) {
        cp_wait0();
        __syncthreads();                   // buffer kt&1 ready; nb free

        const int nb = (kt + 1) & 1;
        const bool more = (kt + 1 < NKCH);

        if (more) {
            const int kn = (kt + 1) * BK;
            if (kt + 1 < NKCH - 1) {
#pragma unroll
                for (int j = 0; j < 8; j++) {
                    int row = aRowL + j * 8;
                    pre[j] = *(const float2*)(Xb + (size_t)row * FIN + kn + aC2 * 2);
                }
            } else {                        // last chunk: k 1216..1279
#pragma unroll
                for (int j = 0; j < 8; j++) {
                    int row = aRowL + j * 8;
                    int k   = kn + aC2 * 2;
                    pre[j] = (k < FIN)
                        ? *(const float2*)(Xb + (size_t)row * FIN + k)
                        : make_float2(0.0f, 0.0f);
                }
            }
#pragma unroll
            for (int j = 0; j < 8; j++) {
                int row = bRowL + j * 32;
                cp_async16(bsB + (uint32_t)(nb * BBUFB + row * ROWB + bG * 16),
                           Wb + (size_t)(bn + row) * KP + kn + bG * 8);
            }
            cp_commit();
        } else {
            cp_commit();
        }

        const uint32_t aBase = asB + (uint32_t)((kt & 1) * ABUFB);
        const uint32_t bBase = bsB + (uint32_t)((kt & 1) * BBUFB);

#pragma unroll
        for (int ks = 0; ks < 4; ks++) {
            uint32_t a[2][4];
#pragma unroll
            for (int mt = 0; mt < 2; mt++) {
                uint32_t addr = aBase + (aRowOff + mt * 16) * ROWB
                                      + ks * 32 + aColOff;
                ldsm_x4(a[mt][0], a[mt][1], a[mt][2], a[mt][3], addr);
            }
            uint32_t b[4][4];
#pragma unroll
            for (int p = 0; p < 4; p++) {
                uint32_t addr = bBase + (bRowOff + p * 16) * ROWB
                                      + ks * 32 + bColOff;
                ldsm_x4(b[p][0], b[p][1], b[p][2], b[p][3], addr);
            }
#pragma unroll
            for (int mt = 0; mt < 2; mt++)
#pragma unroll
                for (int nt = 0; nt < 8; nt++)
                    mma16816(acc[mt][nt], a[mt],
                             b[nt >> 1][(nt & 1) * 2],
                             b[nt >> 1][(nt & 1) * 2 + 1]);
        }

        if (more) {
#pragma unroll
            for (int j = 0; j < 8; j++) {
                int row = aRowL + j * 8;
                __nv_bfloat162 b2 = __float22bfloat162_rn(pre[j]);
                *(__nv_bfloat162*)(As + nb * ABUFB + row * ROWB + aC2 * 4) = b2;
            }
        }
    }

    // epilogue: bf16 stores
    const int cr = lane >> 2;
    const int cc = (lane & 3) * 2;
#pragma unroll
    for (int mt = 0; mt < 2; mt++) {
#pragma unroll
        for (int nt = 0; nt < 8; nt++) {
            int row0 = bm + wm * 32 + mt * 16 + cr;
            int col  = bn + wn * 64 + nt * 8 + cc;
            __nv_bfloat162 v01 = __floats2bfloat162_rn(acc[mt][nt][0], acc[mt][nt][1]);
            __nv_bfloat162 v23 = __floats2bfloat162_rn(acc[mt][nt][2], acc[mt][nt][3]);
            *(__nv_bfloat162*)(U + (size_t)row0 * HH + col)       = v01;
            *(__nv_bfloat162*)(U + (size_t)(row0 + 8) * HH + col) = v23;
        }
    }
}

// ---------------------------------------------------------------------------
// K2: fused PSP + spike scan, layer 1 (bf16 in, bf16 out) — R6-proven:
// one thread per (b,h) chain, 32768 threads, two-named-buffer prefetch,
// static indices only.
// ---------------------------------------------------------------------------
#define SCH 10
__global__ __launch_bounds__(128) void scan1_kernel(
    const __nv_bfloat16* __restrict__ U1, __nv_bfloat16* __restrict__ S1)
{
    const int b = blockIdx.x;
    const int h = blockIdx.y * 128 + threadIdx.x;
    const __nv_bfloat16* up = U1 + (size_t)b * TT * HH + h;
    __nv_bfloat16*       sp = S1 + (size_t)b * TT * HH + h;

    float b0[SCH], b1[SCH];
#pragma unroll
    for (int j = 0; j < SCH; j++) b0[j] = __bfloat162float(up[(size_t)j * HH]);

    float p = 0.0f, r = 0.0f;
    const int NC = TT / SCH;             // 50 (even)
    for (int c = 0; c < NC; c += 2) {
        {
            const __nv_bfloat16* nx = up + (size_t)(c + 1) * SCH * HH;
#pragma unroll
            for (int j = 0; j < SCH; j++) b1[j] = __bfloat162float(nx[(size_t)j * HH]);
        }
        {
            __nv_bfloat16* so = sp + (size_t)c * SCH * HH;
#pragma unroll
            for (int j = 0; j < SCH; j++) {
                p = DSYN * p + b0[j];
                float v = p + r;
                float s = (v >= THETA) ? 1.0f : 0.0f;
                r = DREF * (r - 2.0f * THETA * s);
                so[(size_t)j * HH] = __float2bfloat16(s);
            }
        }
        if (c + 2 < NC) {
            const __nv_bfloat16* nx = up + (size_t)(c + 2) * SCH * HH;
#pragma unroll
            for (int j = 0; j < SCH; j++) b0[j] = __bfloat162float(nx[(size_t)j * HH]);
        }
        {
            __nv_bfloat16* so = sp + (size_t)(c + 1) * SCH * HH;
#pragma unroll
            for (int j = 0; j < SCH; j++) {
                p = DSYN * p + b1[j];
                float v = p + r;
                float s = (v >= THETA) ? 1.0f : 0.0f;
                r = DREF * (r - 2.0f * THETA * s);
                so[(size_t)j * HH] = __float2bfloat16(s);
            }
        }
    }
}

// ---------------------------------------------------------------------------
// K3: U2[m,o] = sum_h S1[m,h] * W2[o,h]. Warp per row (R5/R8-proven):
// lane-strided h = lane + 32i -> conflict-free smem W2, coalesced s1.
// ---------------------------------------------------------------------------
__global__ __launch_bounds__(256) void gemm2_kernel(
    const __nv_bfloat16* __restrict__ S1, const float* __restrict__ W2,
    float* __restrict__ U2)
{
    __shared__ float w2s[OO * HH];
    for (int i = threadIdx.x; i < OO * HH; i += blockDim.x) w2s[i] = W2[i];
    __syncthreads();

    const int gwarp = (blockIdx.x * blockDim.x + threadIdx.x) >> 5;
    const int lane  = threadIdx.x & 31;
    if (gwarp >= MM) return;

    const __nv_bfloat16* s = S1 + (size_t)gwarp * HH;
    float a0 = 0.0f, a1 = 0.0f;
#pragma unroll
    for (int h = lane; h < HH; h += 32) {
        float sv = __bfloat162float(s[h]);
        a0 += sv * w2s[h];
        a1 += sv * w2s[HH + h];
    }
#pragma unroll
    for (int off = 16; off > 0; off >>= 1) {
        a0 += __shfl_xor_sync(0xFFFFFFFFu, a0, off);
        a1 += __shfl_xor_sync(0xFFFFFFFFu, a1, off);
    }
    if (lane == 0) {
        U2[(size_t)gwarp * OO + 0] = a0;
        U2[(size_t)gwarp * OO + 1] = a1;
    }
}

// ---------------------------------------------------------------------------
// K4: scan layer 2. Explicit two-named-buffer pipeline.
// ---------------------------------------------------------------------------
#define SC2 20
__global__ __launch_bounds__(128) void scan2_kernel(
    const float* __restrict__ U2, float* __restrict__ out)
{
    const int i = threadIdx.x;
    const int b = i >> 1;
    const int o = i & 1;
    const float* up = U2  + (size_t)b * TT * OO + o;
    float*       op = out + (size_t)b * TT * OO + o;

    float b0[SC2], b1[SC2];
#pragma unroll
    for (int j = 0; j < SC2; j++) b0[j] = up[(size_t)j * OO];

    float p = 0.0f, r = 0.0f;
    const int NC = TT / SC2;             // 25 (odd)
    for (int c = 0; c < NC; c += 2) {
        if (c + 1 < NC) {
            const float* nx = up + (size_t)(c + 1) * SC2 * OO;
#pragma unroll
            for (int j = 0; j < SC2; j++) b1[j] = nx[(size_t)j * OO];
        }
        {
            float* oo = op + (size_t)c * SC2 * OO;
#pragma unroll
            for (int j = 0; j < SC2; j++) {
                p = DSYN * p + b0[j];
                float v = p + r;
                float s = (v >= THETA) ? 1.0f : 0.0f;
                r = DREF * (r - 2.0f * THETA * s);
                oo[(size_t)j * OO] = s;
            }
        }
        if (c + 2 < NC) {
            const float* nx = up + (size_t)(c + 2) * SC2 * OO;
#pragma unroll
            for (int j = 0; j < SC2; j++) b0[j] = nx[(size_t)j * OO];
        }
        if (c + 1 < NC) {
            float* oo = op + (size_t)(c + 1) * SC2 * OO;
#pragma unroll
            for (int j = 0; j < SC2; j++) {
                p = DSYN * p + b1[j];
                float v = p + r;
                float s = (v >= THETA) ? 1.0f : 0.0f;
                r = DREF * (r - 2.0f * THETA * s);
                oo[(size_t)j * OO] = s;
            }
        }
    }
}

// ---------------------------------------------------------------------------
extern "C" void kernel_launch(void* const* d_in, const int* in_sizes, int n_in,
                              void* d_out, int out_size)
{
    const float* x  = (const float*)d_in[0];   // (64, 500, 1250)
    const float* W1 = (const float*)d_in[1];   // (512, 1250)
    const float* W2 = (const float*)d_in[2];   // (2, 512)
    float* out = (float*)d_out;                // (64, 500, 2)

    __nv_bfloat16* w1b; cudaGetSymbolAddress((void**)&w1b, g_w1b);
    __nv_bfloat16* u1;  cudaGetSymbolAddress((void**)&u1,  g_u1);
    __nv_bfloat16* s1;  cudaGetSymbolAddress((void**)&s1,  g_s1);
    float*         u2;  cudaGetSymbolAddress((void**)&u2,  g_u2);

    {
        long n = (long)HH * KP;
        cvt_w1_kernel<<<(unsigned)((n + 255) / 256), 256>>>(W1, w1b);
    }

    cudaFuncSetAttribute(gemm1_mma_kernel,
                         cudaFuncAttributeMaxDynamicSharedMemorySize, SMEM_GEMM);
    dim3 g1(HH / BN, MM / BM);                // (2, 500)
    gemm1_mma_kernel<<<g1, 256, SMEM_GEMM>>>(x, w1b, u1);

    dim3 g2(BV, HH / 128);                    // (64, 4)
    scan1_kernel<<<g2, 128>>>(u1, s1);

    gemm2_kernel<<<(MM * 32 + 255) / 256, 256>>>(s1, W2, u2);

    scan2_kernel<<<1, 128>>>(u2, out);
}

// round 10
// speedup vs baseline: 2.0472x; 1.0284x over previous
#include <cuda_runtime.h>
#include <cuda_bf16.h>
#include <cuda_fp16.h>
#include <cstdint>

// Problem dims
#define BV   64
#define TT   500
#define FIN  1250
#define KP   1280          // FIN padded for B
#define HH   512
#define OO   2
#define MM   (BV * TT)     // 32000

// Neuron constants
#define DSYN  0.9048374180359595f
#define DREF  0.36787944117144233f
#define THETA 10.0f

// Scratch (device globals: allocation-free rule)
__device__ __align__(16) __half          g_w1h[(size_t)HH * KP];  // 1.3 MB
__device__ __align__(16) __half          g_u1 [(size_t)MM * HH];  // 32 MB (fp16)
__device__ __align__(16) __nv_bfloat16  g_s1 [(size_t)MM * HH];  // 32 MB
__device__ __align__(16) float           g_u2 [(size_t)MM * OO]; // 256 KB

// ---------------------------------------------------------------------------
// PTX helpers
// ---------------------------------------------------------------------------
__device__ __forceinline__ void ldsm_x4(uint32_t &r0, uint32_t &r1,
                                        uint32_t &r2, uint32_t &r3,
                                        uint32_t addr)
{
    asm volatile("ldmatrix.sync.aligned.m8n8.x4.shared.b16 {%0,%1,%2,%3}, [%4];"
                 : "=r"(r0), "=r"(r1), "=r"(r2), "=r"(r3) : "r"(addr));
}

// fp16-accumulator MMA: D(2 regs) = A(4) * B(2) + D
__device__ __forceinline__ void mma16816_f16(uint32_t* c, const uint32_t* a,
                                             const uint32_t b0, const uint32_t b1)
{
    asm volatile(
        "mma.sync.aligned.m16n8k16.row.col.f16.f16.f16.f16 "
        "{%0,%1}, {%2,%3,%4,%5}, {%6,%7}, {%0,%1};"
        : "+r"(c[0]), "+r"(c[1])
        : "r"(a[0]), "r"(a[1]), "r"(a[2]), "r"(a[3]), "r"(b0), "r"(b1));
}

__device__ __forceinline__ void cp_async16(uint32_t smem_addr, const void* gptr)
{
    asm volatile("cp.async.cg.shared.global [%0], [%1], 16;"
                 :: "r"(smem_addr), "l"(gptr));
}
__device__ __forceinline__ void cp_commit()
{
    asm volatile("cp.async.commit_group;");
}
__device__ __forceinline__ void cp_wait0()
{
    asm volatile("cp.async.wait_group 0;");
}

// ---------------------------------------------------------------------------
// K0: W1 fp32 -> fp16, pad K 1250 -> 1280 (L2-resident thereafter)
// ---------------------------------------------------------------------------
__global__ __launch_bounds__(256) void cvt_w1_kernel(
    const float* __restrict__ W, __half* __restrict__ Wh)
{
    long i = (long)blockIdx.x * blockDim.x + threadIdx.x;
    if (i >= (long)HH * KP) return;
    int  k = (int)(i % KP);
    long h = i / KP;
    float v = (k < FIN) ? W[h * FIN + k] : 0.0f;
    Wh[i] = __float2half(v);
}

// ---------------------------------------------------------------------------
// K1: U1[m,h] = sum_k X[m,k] * W1[h,k]   (fp16 HMMA, fp16 accum, fp16 out)
// BM=64, BN=256, BK=64, occ 2. 8 warps as 2(m) x 4(n), warp tile 32x64.
// A: fp32 LDG -> regs -> fp16 STS, one chunk ahead. B: cp.async dbl buffer.
// Rows padded to 72 halves (144B).
// ---------------------------------------------------------------------------
#define BM 64
#define BN 256
#define BK 64
#define LDA 72
#define ROWB (LDA * 2)             // 144 bytes/row
#define ABUFB (BM * ROWB)          // 9216
#define BBUFB (BN * ROWB)          // 36864
#define SMEM_GEMM (2 * ABUFB + 2 * BBUFB)   // 92160
#define NKCH (KP / BK)             // 20

__global__ __launch_bounds__(256, 2) void gemm1_mma_kernel(
    const float* __restrict__ X,
    const __half* __restrict__ Wh,
    __half* __restrict__ U)
{
    extern __shared__ __align__(16) char smem[];
    char* As = smem;
    char* Bs = smem + 2 * ABUFB;

    const int tid  = threadIdx.x;
    const int warp = tid >> 5;
    const int lane = tid & 31;
    const int wm   = warp >> 2;            // 0..1 -> m off wm*32
    const int wn   = warp & 3;             // 0..3 -> n off wn*64
    const int bm   = blockIdx.y * BM;
    const int bn   = blockIdx.x * BN;

    uint32_t acc[2][8][2];                 // fp16x2 accumulators
#pragma unroll
    for (int i = 0; i < 2; i++)
#pragma unroll
        for (int j = 0; j < 8; j++) {
            acc[i][j][0] = 0u;
            acc[i][j][1] = 0u;
        }

    const uint32_t asB = (uint32_t)__cvta_generic_to_shared(As);
    const uint32_t bsB = (uint32_t)__cvta_generic_to_shared(Bs);

    // A: 64 rows x 32 float2 = 2048 units, 8/thread. row=(tid>>5)+j*8, c2=tid&31
    const int aRowL = tid >> 5;
    const int aC2   = tid & 31;
    // B: 256 rows x 128B = 2048 x16B, 8/thread. row=(tid>>3)+j*32, g=tid&7
    const int bRowL = tid >> 3;
    const int bG    = tid & 7;

    const float* Xb = X + (size_t)bm * FIN;

    float2 pre[8];

    // ---- preload chunk 0
    {
#pragma unroll
        for (int j = 0; j < 8; j++) {
            int row = aRowL + j * 8;
            pre[j] = *(const float2*)(Xb + (size_t)row * FIN + aC2 * 2);
        }
#pragma unroll
        for (int j = 0; j < 8; j++) {
            int row = aRowL + j * 8;
            __half2 h2 = __float22half2_rn(pre[j]);
            *(__half2*)(As + row * ROWB + aC2 * 4) = h2;
        }
#pragma unroll
        for (int j = 0; j < 8; j++) {
            int row = bRowL + j * 32;
            cp_async16(bsB + (uint32_t)(row * ROWB + bG * 16),
                       Wh + (size_t)(bn + row) * KP + bG * 8);
        }
        cp_commit();
    }

    const uint32_t aRowOff = (uint32_t)(wm * 32 + (lane & 15));
    const uint32_t aColOff = (uint32_t)((lane >> 4) * 16);
    const uint32_t bRowOff = (uint32_t)(wn * 64 + ((lane >> 4) & 1) * 8 + (lane & 7));
    const uint32_t bColOff = (uint32_t)(((lane >> 3) & 1) * 16);

    for (int kt = 0; kt < NKCH; kt++) {
        cp_wait0();
        __syncthreads();                   // buffer kt&1 ready; nb free

        const int nb = (kt + 1) & 1;
        const bool more = (kt + 1 < NKCH);

        if (more) {
            const int kn = (kt + 1) * BK;
            if (kt + 1 < NKCH - 1) {
#pragma unroll
                for (int j = 0; j < 8; j++) {
                    int row = aRowL + j * 8;
                    pre[j] = *(const float2*)(Xb + (size_t)row * FIN + kn + aC2 * 2);
                }
            } else {                        // last chunk: k 1216..1279
#pragma unroll
                for (int j = 0; j < 8; j++) {
                    int row = aRowL + j * 8;
                    int k   = kn + aC2 * 2;
                    pre[j] = (k < FIN)
                        ? *(const float2*)(Xb + (size_t)row * FIN + k)
                        : make_float2(0.0f, 0.0f);
                }
            }
#pragma unroll
            for (int j = 0; j < 8; j++) {
                int row = bRowL + j * 32;
                cp_async16(bsB + (uint32_t)(nb * BBUFB + row * ROWB + bG * 16),
                           Wh + (size_t)(bn + row) * KP + kn + bG * 8);
            }
            cp_commit();
        } else {
            cp_commit();
        }

        const uint32_t aBase = asB + (uint32_t)((kt & 1) * ABUFB);
        const uint32_t bBase = bsB + (uint32_t)((kt & 1) * BBUFB);

#pragma unroll
        for (int ks = 0; ks < 4; ks++) {
            uint32_t a[2][4];
#pragma unroll
            for (int mt = 0; mt < 2; mt++) {
                uint32_t addr = aBase + (aRowOff + mt * 16) * ROWB
                                      + ks * 32 + aColOff;
                ldsm_x4(a[mt][0], a[mt][1], a[mt][2], a[mt][3], addr);
            }
            uint32_t b[4][4];
#pragma unroll
            for (int p = 0; p < 4; p++) {
                uint32_t addr = bBase + (bRowOff + p * 16) * ROWB
                                      + ks * 32 + bColOff;
                ldsm_x4(b[p][0], b[p][1], b[p][2], b[p][3], addr);
            }
#pragma unroll
            for (int mt = 0; mt < 2; mt++)
#pragma unroll
                for (int nt = 0; nt < 8; nt++)
                    mma16816_f16(acc[mt][nt], a[mt],
                                 b[nt >> 1][(nt & 1) * 2],
                                 b[nt >> 1][(nt & 1) * 2 + 1]);
        }

        if (more) {
#pragma unroll
            for (int j = 0; j < 8; j++) {
                int row = aRowL + j * 8;
                __half2 h2 = __float22half2_rn(pre[j]);
                *(__half2*)(As + nb * ABUFB + row * ROWB + aC2 * 4) = h2;
            }
        }
    }

    // epilogue: raw fp16x2 stores (frag reg0 -> row, reg1 -> row+8)
    const int cr = lane >> 2;
    const int cc = (lane & 3) * 2;
#pragma unroll
    for (int mt = 0; mt < 2; mt++) {
#pragma unroll
        for (int nt = 0; nt < 8; nt++) {
            int row0 = bm + wm * 32 + mt * 16 + cr;
            int col  = bn + wn * 64 + nt * 8 + cc;
            *(uint32_t*)(U + (size_t)row0 * HH + col)       = acc[mt][nt][0];
            *(uint32_t*)(U + (size_t)(row0 + 8) * HH + col) = acc[mt][nt][1];
        }
    }
}

// ---------------------------------------------------------------------------
// K2: fused PSP + spike scan, layer 1 (fp16 in, bf16 out).
// One thread per (b,h) chain, two-named-buffer prefetch, static indices.
// ---------------------------------------------------------------------------
#define SCH 10
__global__ __launch_bounds__(128) void scan1_kernel(
    const __half* __restrict__ U1, __nv_bfloat16* __restrict__ S1)
{
    const int b = blockIdx.x;
    const int h = blockIdx.y * 128 + threadIdx.x;
    const __half*        up = U1 + (size_t)b * TT * HH + h;
    __nv_bfloat16*       sp = S1 + (size_t)b * TT * HH + h;

    float b0[SCH], b1[SCH];
#pragma unroll
    for (int j = 0; j < SCH; j++) b0[j] = __half2float(up[(size_t)j * HH]);

    float p = 0.0f, r = 0.0f;
    const int NC = TT / SCH;             // 50 (even)
    for (int c = 0; c < NC; c += 2) {
        {
            const __half* nx = up + (size_t)(c + 1) * SCH * HH;
#pragma unroll
            for (int j = 0; j < SCH; j++) b1[j] = __half2float(nx[(size_t)j * HH]);
        }
        {
            __nv_bfloat16* so = sp + (size_t)c * SCH * HH;
#pragma unroll
            for (int j = 0; j < SCH; j++) {
                p = DSYN * p + b0[j];
                float v = p + r;
                float s = (v >= THETA) ? 1.0f : 0.0f;
                r = DREF * (r - 2.0f * THETA * s);
                so[(size_t)j * HH] = __float2bfloat16(s);
            }
        }
        if (c + 2 < NC) {
            const __half* nx = up + (size_t)(c + 2) * SCH * HH;
#pragma unroll
            for (int j = 0; j < SCH; j++) b0[j] = __half2float(nx[(size_t)j * HH]);
        }
        {
            __nv_bfloat16* so = sp + (size_t)(c + 1) * SCH * HH;
#pragma unroll
            for (int j = 0; j < SCH; j++) {
                p = DSYN * p + b1[j];
                float v = p + r;
                float s = (v >= THETA) ? 1.0f : 0.0f;
                r = DREF * (r - 2.0f * THETA * s);
                so[(size_t)j * HH] = __float2bfloat16(s);
            }
        }
    }
}

// ---------------------------------------------------------------------------
// K3: U2[m,o] = sum_h S1[m,h] * W2[o,h]. Warp per row (proven pattern):
// lane-strided h = lane + 32i -> conflict-free smem W2, coalesced s1.
// ---------------------------------------------------------------------------
__global__ __launch_bounds__(256) void gemm2_kernel(
    const __nv_bfloat16* __restrict__ S1, const float* __restrict__ W2,
    float* __restrict__ U2)
{
    __shared__ float w2s[OO * HH];
    for (int i = threadIdx.x; i < OO * HH; i += blockDim.x) w2s[i] = W2[i];
    __syncthreads();

    const int gwarp = (blockIdx.x * blockDim.x + threadIdx.x) >> 5;
    const int lane  = threadIdx.x & 31;
    if (gwarp >= MM) return;

    const __nv_bfloat16* s = S1 + (size_t)gwarp * HH;
    float a0 = 0.0f, a1 = 0.0f;
#pragma unroll
    for (int h = lane; h < HH; h += 32) {
        float sv = __bfloat162float(s[h]);
        a0 += sv * w2s[h];
        a1 += sv * w2s[HH + h];
    }
#pragma unroll
    for (int off = 16; off > 0; off >>= 1) {
        a0 += __shfl_xor_sync(0xFFFFFFFFu, a0, off);
        a1 += __shfl_xor_sync(0xFFFFFFFFu, a1, off);
    }
    if (lane == 0) {
        U2[(size_t)gwarp * OO + 0] = a0;
        U2[(size_t)gwarp * OO + 1] = a1;
    }
}

// ---------------------------------------------------------------------------
// K4: scan layer 2. Explicit two-named-buffer pipeline.
// ---------------------------------------------------------------------------
#define SC2 20
__global__ __launch_bounds__(128) void scan2_kernel(
    const float* __restrict__ U2, float* __restrict__ out)
{
    const int i = threadIdx.x;
    const int b = i >> 1;
    const int o = i & 1;
    const float* up = U2  + (size_t)b * TT * OO + o;
    float*       op = out + (size_t)b * TT * OO + o;

    float b0[SC2], b1[SC2];
#pragma unroll
    for (int j = 0; j < SC2; j++) b0[j] = up[(size_t)j * OO];

    float p = 0.0f, r = 0.0f;
    const int NC = TT / SC2;             // 25 (odd)
    for (int c = 0; c < NC; c += 2) {
        if (c + 1 < NC) {
            const float* nx = up + (size_t)(c + 1) * SC2 * OO;
#pragma unroll
            for (int j = 0; j < SC2; j++) b1[j] = nx[(size_t)j * OO];
        }
        {
            float* oo = op + (size_t)c * SC2 * OO;
#pragma unroll
            for (int j = 0; j < SC2; j++) {
                p = DSYN * p + b0[j];
                float v = p + r;
                float s = (v >= THETA) ? 1.0f : 0.0f;
                r = DREF * (r - 2.0f * THETA * s);
                oo[(size_t)j * OO] = s;
            }
        }
        if (c + 2 < NC) {
            const float* nx = up + (size_t)(c + 2) * SC2 * OO;
#pragma unroll
            for (int j = 0; j < SC2; j++) b0[j] = nx[(size_t)j * OO];
        }
        if (c + 1 < NC) {
            float* oo = op + (size_t)(c + 1) * SC2 * OO;
#pragma unroll
            for (int j = 0; j < SC2; j++) {
                p = DSYN * p + b1[j];
                float v = p + r;
                float s = (v >= THETA) ? 1.0f : 0.0f;
                r = DREF * (r - 2.0f * THETA * s);
                oo[(size_t)j * OO] = s;
            }
        }
    }
}

// ---------------------------------------------------------------------------
extern "C" void kernel_launch(void* const* d_in, const int* in_sizes, int n_in,
                              void* d_out, int out_size)
{
    const float* x  = (const float*)d_in[0];   // (64, 500, 1250)
    const float* W1 = (const float*)d_in[1];   // (512, 1250)
    const float* W2 = (const float*)d_in[2];   // (2, 512)
    float* out = (float*)d_out;                // (64, 500, 2)

    __half*        w1h; cudaGetSymbolAddress((void**)&w1h, g_w1h);
    __half*        u1;  cudaGetSymbolAddress((void**)&u1,  g_u1);
    __nv_bfloat16* s1;  cudaGetSymbolAddress((void**)&s1,  g_s1);
    float*         u2;  cudaGetSymbolAddress((void**)&u2,  g_u2);

    {
        long n = (long)HH * KP;
        cvt_w1_kernel<<<(unsigned)((n + 255) / 256), 256>>>(W1, w1h);
    }

    cudaFuncSetAttribute(gemm1_mma_kernel,
                         cudaFuncAttributeMaxDynamicSharedMemorySize, SMEM_GEMM);
    dim3 g1(HH / BN, MM / BM);                // (2, 500)
    gemm1_mma_kernel<<<g1, 256, SMEM_GEMM>>>(x, w1h, u1);

    dim3 g2(BV, HH / 128);                    // (64, 4)
    scan1_kernel<<<g2, 128>>>(u1, s1);

    gemm2_kernel<<<(MM * 32 + 255) / 256, 256>>>(s1, W2, u2);

    scan2_kernel<<<1, 128>>>(u2, out);
}